// round 8
// baseline (speedup 1.0000x reference)
#include <cuda_runtime.h>
#include <cstdint>

// out[b, 0:128]   = x[b, :]                       for b < B
// out[b, 128:256] = sum_{e: dst[e]==b} x[src[e]]
//
// Pipeline:
//   memset:  zero overflow counter only (4 bytes). g_cnt self-cleaned by
//            main_kernel each call (statically zero-init; every call restores).
//   K1 bin:  ELL binning by destination (scalar, one edge per thread).
//   K2 main: ONE FULL WARP per row (max TLP — the measured winner), simple
//            gather loop with a depth-2 software pipeline: next iteration's
//            load issues before the current adds. Fused copy of x[b];
//            overflow rows scan the overflow list in-warp. No atomics.

#define NFEAT   128
#define ROW_OUT 256
#define MAX_E   640000
#define B_MAX   65536
#define SLOTS   32

__device__ int  g_cnt[B_MAX];
__device__ int  g_ell[B_MAX * SLOTS];
__device__ int2 g_ovf[MAX_E];
__device__ int  g_ovf_count;

__global__ void bin_kernel(const int* __restrict__ ei, int E, int B) {
    int i = blockIdx.x * blockDim.x + threadIdx.x;
    if (i >= E) return;
    int d = __ldg(ei + E + i);
    if ((unsigned)d < (unsigned)B) {
        int s = __ldg(ei + i);
        int k = atomicAdd(&g_cnt[d], 1);
        if (k < SLOTS) {
            g_ell[d * SLOTS + k] = s;
        } else {
            int p = atomicAdd(&g_ovf_count, 1);
            g_ovf[p] = make_int2(s, d);
        }
    }
}

__global__ __launch_bounds__(256)
void main_kernel(const float* __restrict__ x,
                 float* __restrict__ out,
                 int B) {
    int warp = (blockIdx.x * blockDim.x + threadIdx.x) >> 5;
    int lane = threadIdx.x & 31;
    if (warp >= B) return;
    int b = warp;

    int c_raw = g_cnt[b];
    int c = c_raw < SLOTS ? c_raw : SLOTS;
    if (lane == 0) g_cnt[b] = 0;          // self-clean for next graph replay

    // Coalesced preload of this row's source list (one slot per lane).
    int src_l = (lane < c) ? g_ell[b * SLOTS + lane] : 0;

    float4 acc = make_float4(0.f, 0.f, 0.f, 0.f);

    // Depth-2 software pipeline: load(k+1) issues before acc += load(k).
    if (c > 0) {
        int se0 = __shfl_sync(0xFFFFFFFFu, src_l, 0);
        float4 vcur = __ldg(reinterpret_cast<const float4*>(
                                x + (size_t)se0 * NFEAT) + lane);
        for (int k = 1; k < c; k++) {
            int se = __shfl_sync(0xFFFFFFFFu, src_l, k);
            float4 vnext = __ldg(reinterpret_cast<const float4*>(
                                     x + (size_t)se * NFEAT) + lane);
            acc.x += vcur.x; acc.y += vcur.y;
            acc.z += vcur.z; acc.w += vcur.w;
            vcur = vnext;
        }
        acc.x += vcur.x; acc.y += vcur.y;
        acc.z += vcur.z; acc.w += vcur.w;
    }

    // Rare path: degree exceeded SLOTS -> extras live in the overflow list.
    if (c_raw > SLOTS) {
        int n = g_ovf_count;
        for (int e = 0; e < n; e++) {
            int2 ed = g_ovf[e];
            if (ed.y == b) {
                float4 v = __ldg(reinterpret_cast<const float4*>(
                                     x + (size_t)ed.x * NFEAT) + lane);
                acc.x += v.x; acc.y += v.y; acc.z += v.z; acc.w += v.w;
            }
        }
    }

    // Fused: first half = x[b], second half = neighbor sum.
    float4 mine = __ldg(reinterpret_cast<const float4*>(
                            x + (size_t)b * NFEAT) + lane);
    float4* orow = reinterpret_cast<float4*>(out + (size_t)b * ROW_OUT);
    orow[lane]               = mine;
    orow[(NFEAT / 4) + lane] = acc;
}

extern "C" void kernel_launch(void* const* d_in, const int* in_sizes, int n_in,
                              void* d_out, int out_size) {
    const float* x        = (const float*)d_in[0];
    const int*   edge_idx = (const int*)d_in[1];
    float*       out      = (float*)d_out;

    int B = out_size / ROW_OUT;          // 50000
    int E = in_sizes[1] / 2;             // 640000

    // Only the 4-byte overflow counter needs a memset node.
    void* p_ovfc = nullptr;
    cudaGetSymbolAddress(&p_ovfc, g_ovf_count);
    cudaMemsetAsync(p_ovfc, 0, sizeof(int));

    {   // K1: ELL binning (one edge per thread)
        int threads = 256;
        int blocks = (E + threads - 1) / threads;
        bin_kernel<<<blocks, threads>>>(edge_idx, E, B);
    }
    {   // K2: main fused gather-accumulate-store, one full warp per row
        int threads = 256;                          // 8 warps/block
        int blocks = (B + 7) / 8;
        main_kernel<<<blocks, threads>>>(x, out, B);
    }
}